// round 5
// baseline (speedup 1.0000x reference)
#include <cuda_runtime.h>
#include <math.h>

#define N_SAMPLES 262144
#define N_FLOAT4 (N_SAMPLES / 4)                  // 65536
#define N_K 128
#define N_STEPS 1024
#define K_TILE 16
#define NPAIR (K_TILE / 2)                        // 8 packed harmonic pairs
#define N_TILES (N_K / K_TILE)                    // 8
#define CHUNKS 37
#define TOTAL_BLOCKS (N_TILES * CHUNKS)           // 296 = 2 per SM
#define THREADS1 256
#define NACC (4 * K_TILE)                         // 64
#define VALS (NACC + 1)                           // 65
#define TWO_PI 6.2831855f

typedef unsigned long long u64;

// Packed f32x2 helpers (FFMA2 path — only reachable via PTX)
__device__ __forceinline__ u64 pk(float lo, float hi) {
    u64 r; asm("mov.b64 %0, {%1, %2};" : "=l"(r) : "f"(lo), "f"(hi)); return r;
}
__device__ __forceinline__ void upk(u64 v, float& lo, float& hi) {
    asm("mov.b64 {%0, %1}, %2;" : "=f"(lo), "=f"(hi) : "l"(v));
}
__device__ __forceinline__ u64 f2fma(u64 a, u64 b, u64 c) {
    u64 d; asm("fma.rn.f32x2 %0, %1, %2, %3;" : "=l"(d) : "l"(a), "l"(b), "l"(c)); return d;
}
__device__ __forceinline__ u64 f2add(u64 a, u64 b) {
    u64 d; asm("add.rn.f32x2 %0, %1, %2;" : "=l"(d) : "l"(a), "l"(b)); return d;
}
__device__ __forceinline__ u64 f2mul(u64 a, u64 b) {
    u64 d; asm("mul.rn.f32x2 %0, %1, %2;" : "=l"(d) : "l"(a), "l"(b)); return d;
}

__device__ float g_scratch[N_TILES * CHUNKS * VALS];
__device__ float g_coef[N_TILES * VALS];
__device__ float g_posn[N_STEPS + 2], g_negn[N_STEPS + 2];
__device__ unsigned int g_cnt1 = 0, g_cnt2 = 0, g_cnt3 = 0;

// ---------------------------------------------------------------------------
// Single fused kernel. Grid (37 chunks, 8 tiles) = 296 blocks, 2 per SM,
// all co-resident (launch_bounds(256,2)) -> grid-wide spin barriers are safe.
// Phase 1: packed-f32x2 Fourier reduction (2 independent chains, step 4*theta)
// Phase 2: 8 tile-leader blocks fold chunk partials -> g_coef
// Phase 3: all blocks: normalize coefficients, evaluate CDF steps (strided)
// Phase 4: block 0 computes the AUC scalar, resets counters.
// ---------------------------------------------------------------------------
__global__ void __launch_bounds__(THREADS1, 2)
fused_kernel(const float4* __restrict__ scores4, const uint4* __restrict__ targets4,
             float* __restrict__ out)
{
    const int chunk = blockIdx.x;
    const int tile  = blockIdx.y;
    const int tid   = threadIdx.x;
    const int bid   = tile * CHUNKS + chunk;

    // ------------------ Phase 1: reduction ------------------
    u64 aTS[NPAIR], aTC[NPAIR], aPS[NPAIR], aPC[NPAIR];
#pragma unroll
    for (int p = 0; p < NPAIR; ++p) { aTS[p] = 0; aTC[p] = 0; aPS[p] = 0; aPC[p] = 0; }
    float cnt = 0.f;

    const float k0f = (float)(tile * K_TILE + 1);
    const int start4 = (chunk * N_FLOAT4) / CHUNKS;
    const int end4   = ((chunk + 1) * N_FLOAT4) / CHUNKS;

    for (int i = start4 + tid; i < end4; i += THREADS1) {
        const float4 sv = scores4[i];
        const uint4  tv = targets4[i];
        const float scs[4] = {sv.x, sv.y, sv.z, sv.w};
        const float msk[4] = {tv.x ? 1.f : 0.f, tv.y ? 1.f : 0.f,
                              tv.z ? 1.f : 0.f, tv.w ? 1.f : 0.f};
#pragma unroll
        for (int e = 0; e < 4; ++e) {
            const float sc = scs[e];
            const float m  = msk[e];
            cnt += m;

            const float th = TWO_PI * sc;
            float s1, c1;
            __sincosf(th, &s1, &c1);
            float sA, cA;                          // harmonic k0
            __sincosf(k0f * th, &sA, &cA);
            const float sB = fmaf(sA, c1,  cA * s1);   // k0+1
            const float cB = fmaf(cA, c1, -sA * s1);
            const float s2 = 2.f * s1 * c1;            // 2*theta
            const float c2 = fmaf(c1, c1, -s1 * s1);
            const float s4 = 2.f * s2 * c2;            // 4*theta (chain step)
            const float c4 = fmaf(c2, c2, -s2 * s2);
            const float sC = fmaf(sA, c2,  cA * s2);   // k0+2
            const float cC = fmaf(cA, c2, -sA * s2);
            const float sD = fmaf(sB, c2,  cB * s2);   // k0+3
            const float cD = fmaf(cB, c2, -sB * s2);

            u64 sp0 = pk(sA, sB), cp0 = pk(cA, cB);    // chain 0: pairs 0,2,4,6
            u64 sp1 = pk(sC, sD), cp1 = pk(cC, cD);    // chain 1: pairs 1,3,5,7
            const u64 c4p  = pk(c4, c4);
            const u64 s4p  = pk(s4, s4);
            const u64 ns4p = pk(-s4, -s4);
            const u64 mp   = pk(m, m);

#pragma unroll
            for (int j = 0; j < 4; ++j) {
                const int p0 = 2 * j, p1 = 2 * j + 1;
                aTS[p0] = f2add(aTS[p0], sp0);
                aTC[p0] = f2add(aTC[p0], cp0);
                aPS[p0] = f2fma(mp, sp0, aPS[p0]);
                aPC[p0] = f2fma(mp, cp0, aPC[p0]);
                aTS[p1] = f2add(aTS[p1], sp1);
                aTC[p1] = f2add(aTC[p1], cp1);
                aPS[p1] = f2fma(mp, sp1, aPS[p1]);
                aPC[p1] = f2fma(mp, cp1, aPC[p1]);
                if (j < 3) {
                    const u64 t0 = f2mul(cp0, s4p);
                    const u64 u0 = f2mul(sp0, ns4p);
                    sp0 = f2fma(sp0, c4p, t0);
                    cp0 = f2fma(cp0, c4p, u0);
                    const u64 t1 = f2mul(cp1, s4p);
                    const u64 u1 = f2mul(sp1, ns4p);
                    sp1 = f2fma(sp1, c4p, t1);
                    cp1 = f2fma(cp1, c4p, u1);
                }
            }
        }
    }

    // Pair q holds harmonics k0+2q, k0+2q+1 (chain interleave preserves this).
    __shared__ float red[THREADS1 / 32][VALS];
    const int lane = tid & 31, wid = tid >> 5;
#pragma unroll
    for (int q = 0; q < NPAIR; ++q) {
        u64 a0 = aTS[q], a1 = aTC[q], a2 = aPS[q], a3 = aPC[q];
#pragma unroll
        for (int o = 16; o > 0; o >>= 1) {
            a0 = f2add(a0, __shfl_down_sync(0xffffffffu, a0, o));
            a1 = f2add(a1, __shfl_down_sync(0xffffffffu, a1, o));
            a2 = f2add(a2, __shfl_down_sync(0xffffffffu, a2, o));
            a3 = f2add(a3, __shfl_down_sync(0xffffffffu, a3, o));
        }
        if (lane == 0) {
            float lo, hi;
            upk(a0, lo, hi); red[wid][(2*q)*4 + 0] = lo; red[wid][(2*q+1)*4 + 0] = hi;
            upk(a1, lo, hi); red[wid][(2*q)*4 + 1] = lo; red[wid][(2*q+1)*4 + 1] = hi;
            upk(a2, lo, hi); red[wid][(2*q)*4 + 2] = lo; red[wid][(2*q+1)*4 + 2] = hi;
            upk(a3, lo, hi); red[wid][(2*q)*4 + 3] = lo; red[wid][(2*q+1)*4 + 3] = hi;
        }
    }
    {
        float v = cnt;
#pragma unroll
        for (int o = 16; o > 0; o >>= 1)
            v += __shfl_down_sync(0xffffffffu, v, o);
        if (lane == 0) red[wid][NACC] = v;
    }
    __syncthreads();
    if (tid < VALS) {
        float s = 0.f;
#pragma unroll
        for (int w = 0; w < THREADS1 / 32; ++w) s += red[w][tid];
        g_scratch[(tile * CHUNKS + chunk) * VALS + tid] = s;
    }

    // ------------------ Barrier 1 (all 296 arrive, all poll) ------------------
    __threadfence();
    __syncthreads();
    if (tid == 0) {
        atomicAdd(&g_cnt1, 1u);
        volatile unsigned int* p = &g_cnt1;
        while (*p < TOTAL_BLOCKS) {}
    }
    __syncthreads();
    __threadfence();

    // ------------------ Phase 2: tile leaders fold chunks ------------------
    if (chunk == 0) {
        if (tid < VALS) {
            float s = 0.f;
            const float* base = &g_scratch[tile * CHUNKS * VALS + tid];
#pragma unroll 4
            for (int c = 0; c < CHUNKS; ++c) s += base[c * VALS];
            g_coef[tile * VALS + tid] = s;
        }
        __threadfence();
        __syncthreads();
        if (tid == 0) atomicAdd(&g_cnt2, 1u);
    }
    // ------------------ Barrier 2 (8 leaders arrive, all poll) ------------------
    if (tid == 0) {
        volatile unsigned int* p = &g_cnt2;
        while (*p < N_TILES) {}
    }
    __syncthreads();
    __threadfence();

    // ------------------ Phase 3: coefficients + CDF ------------------
    __shared__ float sisp[N_K], sicp[N_K], sisn[N_K], sicn[N_K];
    if (tid < N_K) {
        const float EPS = 1.1920929e-7f;
        const int tl = tid / K_TILE, j = tid % K_TILE;
        const float tpk = TWO_PI * (float)(tid + 1);
        const float npos = g_coef[NACC];          // tile 0 count = total positives
        const float nneg = (float)N_SAMPLES - npos;

        const float tot_s = g_coef[tl * VALS + j * 4 + 0];
        const float tot_c = g_coef[tl * VALS + j * 4 + 1];
        const float pos_s = g_coef[tl * VALS + j * 4 + 2];
        const float pos_c = g_coef[tl * VALS + j * 4 + 3];

        const float ps  = (npos < EPS) ? 0.f : pos_s / fmaxf(npos, EPS);
        const float pc  = (npos < EPS) ? 0.f : pos_c / fmaxf(npos, EPS);
        const float nsn = (nneg < EPS) ? 0.f : (tot_s - pos_s) / fmaxf(nneg, EPS);
        const float ncn = (nneg < EPS) ? 0.f : (tot_c - pos_c) / fmaxf(nneg, EPS);

        sisp[tid] =  pc / tpk;
        sicp[tid] = -ps / tpk;
        sisn[tid] =  ncn / tpk;
        sicn[tid] = -nsn / tpk;
    }
    __syncthreads();

    // CDF steps: warp w of this block handles step = bid + 296*w (w = 0..3)
    {
        const int step = bid + TOTAL_BLOCKS * wid;
        if (step < N_STEPS) {
            const float thr = (float)step / 1023.0f;
            float cdfp = 0.f, cdfn = 0.f;
#pragma unroll
            for (int i = 0; i < 4; ++i) {
                const int k = lane + i * 32;
                const float tpk = TWO_PI * (float)(k + 1);
                float s, c;
                __sincosf(thr * tpk, &s, &c);
                cdfp = fmaf(s, sisp[k], fmaf(c, sicp[k], cdfp));
                cdfn = fmaf(s, sisn[k], fmaf(c, sicn[k], cdfn));
            }
#pragma unroll
            for (int o = 16; o > 0; o >>= 1) {
                cdfp += __shfl_down_sync(0xffffffffu, cdfp, o);
                cdfn += __shfl_down_sync(0xffffffffu, cdfn, o);
            }
            if (lane == 0) {
                g_posn[step + 1] = 1.0f - 0.5f * (cdfp + 0.5f);
                g_negn[step + 1] = 1.0f - 0.5f * (cdfn + 0.5f);
            }
        }
        if (bid == 0 && tid == 0) {
            g_posn[0] = 1.0f; g_negn[0] = 1.0f;
            g_posn[N_STEPS + 1] = 0.0f; g_negn[N_STEPS + 1] = 0.0f;
        }
    }

    // ------------------ Barrier 3 (all arrive, only block 0 polls) --------------
    __threadfence();
    __syncthreads();
    if (tid == 0) atomicAdd(&g_cnt3, 1u);
    if (bid != 0) return;

    if (tid == 0) {
        volatile unsigned int* p = &g_cnt3;
        while (*p < TOTAL_BLOCKS) {}
    }
    __syncthreads();
    __threadfence();

    // ------------------ Phase 4: AUC (block 0) ------------------
    __shared__ float redA[THREADS1 / 32], redB[THREADS1 / 32];
    float tp = 0.f, tn = 0.f;
    for (int i = tid; i < N_STEPS + 1; i += THREADS1) {
        const float p0 = g_posn[i], p1 = g_posn[i + 1];
        const float q0 = g_negn[i], q1 = g_negn[i + 1];
        tp = fmaf(p0, q0 - q1, tp);
        tn = fmaf(q0, p1 - p0, tn);
    }
#pragma unroll
    for (int o = 16; o > 0; o >>= 1) {
        tp += __shfl_down_sync(0xffffffffu, tp, o);
        tn += __shfl_down_sync(0xffffffffu, tn, o);
    }
    if (lane == 0) { redA[wid] = tp; redB[wid] = tn; }
    __syncthreads();
    if (tid == 0) {
        float a = 0.f, b = 0.f;
#pragma unroll
        for (int w = 0; w < THREADS1 / 32; ++w) { a += redA[w]; b += redB[w]; }
        out[0] = 0.5f * (a + (1.0f + b));
        g_cnt1 = 0; g_cnt2 = 0; g_cnt3 = 0;       // self-reset for graph replay
    }
}

extern "C" void kernel_launch(void* const* d_in, const int* in_sizes, int n_in,
                              void* d_out, int out_size)
{
    (void)in_sizes; (void)n_in; (void)out_size;
    const float4* scores4  = (const float4*)d_in[0];
    const uint4*  targets4 = (const uint4*)d_in[1];
    float* out = (float*)d_out;

    dim3 grid(CHUNKS, N_TILES);
    fused_kernel<<<grid, THREADS1>>>(scores4, targets4, out);
}